// round 17
// baseline (speedup 1.0000x reference)
#include <cuda_runtime.h>
#include <cuda_bf16.h>
#include <mma.h>
#include <math.h>
#include <stdint.h>

using namespace nvcuda;

// Problem constants
#define NUM_B   2
#define NUM_N   16384
#define NUM_DIN 1024
#define NUM_H   512
#define NUM_C   11
#define NUM_K   100
#define CAND    (NUM_N * (NUM_C - 1))
#define ROWS    (NUM_B * NUM_N)         // 32768
#define NCLS    (NUM_C - 1)
#define SEG     NUM_N
#define SCHUNK  (SEG / 64)
#define PHASE1  28

// ---------------- scratch (static device globals; no allocs) ----------------
__device__ __nv_bfloat16 g_xs[3][(size_t)ROWS * NUM_DIN];
__device__ __nv_bfloat16 g_h1s[3][(size_t)ROWS * NUM_H];
__device__ __nv_bfloat16 g_h2s[3][(size_t)ROWS * NUM_H];
__device__ __nv_bfloat16 g_wt1[3][(size_t)NUM_H * NUM_DIN];   // w1^T [512,1024]
__device__ __nv_bfloat16 g_wt2[3][(size_t)NUM_H * NUM_H];     // w2^T [512,512]
__device__ __nv_bfloat16 g_wtp[3][(size_t)128 * NUM_H];       // heads^T [128,512]
__device__ float g_bpad[128];
__device__ float g_h1[(size_t)ROWS * 128];                    // heads out fp32
__device__ float4 g_box4[NUM_B * CAND];
__device__ float  g_box9[(size_t)NUM_B * CAND * 9];
__device__ float  g_raw[NUM_B * CAND];
__device__ float  g_mask[NUM_B * CAND];
__device__ unsigned int g_maxbits;
__device__ unsigned long long g_keys[NUM_B][NCLS][NUM_K];
__device__ float4 g_pick[NUM_B][NCLS][NUM_K];
__device__ int g_cnt[NUM_B][NCLS];
__device__ int g_need[NUM_B][NCLS];

__device__ __forceinline__ void split3(float v, __nv_bfloat16& s0,
                                       __nv_bfloat16& s1, __nv_bfloat16& s2) {
    s0 = __float2bfloat16(v);
    float r1 = v - __bfloat162float(s0);
    s1 = __float2bfloat16(r1);
    s2 = __float2bfloat16(r1 - __bfloat162float(s1));
}

// ======== wmma bf16 split GEMM: C[M,N] = A[M,K] @ W[K,N] + bias ============
// A as 3 bf16 split arrays [M,K] row-major; W as 3 transposed splits [N,K]
// (= B col_major with ldm=K). 6 products in fp32 accum:
//   (a0)(b0+b1+b2) + (a1)(b0+b1) + (a2)(b0)   [sa+sb<=2]
// CTA tile 128x128, 8 warps (warp = 32x64 = 2x4 wmma frags), K-tile 16.
#define WKT 16
#define WLDM 24   // padded smem leading dim (multiple of 8 elems, 48B rows)

__global__ __launch_bounds__(256, 2)
void gemm_wmma(const __nv_bfloat16* __restrict__ a0, const __nv_bfloat16* __restrict__ a1,
               const __nv_bfloat16* __restrict__ a2,
               const __nv_bfloat16* __restrict__ b0, const __nv_bfloat16* __restrict__ b1,
               const __nv_bfloat16* __restrict__ b2,
               const float* __restrict__ bias, int K, int NFull,
               float* __restrict__ outF,
               __nv_bfloat16* __restrict__ o0, __nv_bfloat16* __restrict__ o1,
               __nv_bfloat16* __restrict__ o2, int doRelu)
{
    __shared__ __align__(16) __nv_bfloat16 sA[3][128][WLDM];
    __shared__ __align__(16) __nv_bfloat16 sB[3][128][WLDM];
    __shared__ __align__(16) float stage[8][256];

    const int tid = threadIdx.x;
    const int wid = tid >> 5;
    const int lid = tid & 31;
    const int wm = wid & 3;          // m quarter (32 rows)
    const int wn = wid >> 2;         // n half (64 cols)
    const int bm = blockIdx.y * 128;
    const int bn = blockIdx.x * 128;

    const __nv_bfloat16* Aps[3] = {a0, a1, a2};
    const __nv_bfloat16* Bps[3] = {b0, b1, b2};

    wmma::fragment<wmma::accumulator, 16, 16, 16, float> acc[2][4];
#pragma unroll
    for (int i = 0; i < 2; i++)
#pragma unroll
        for (int j = 0; j < 4; j++) wmma::fill_fragment(acc[i][j], 0.0f);

    const int row = tid >> 1;            // 0..127
    const int half = tid & 1;            // which 8-elem chunk of the 16-k tile

    for (int k0 = 0; k0 < K; k0 += WKT) {
#pragma unroll
        for (int s = 0; s < 3; s++) {
            *(uint4*)&sA[s][row][half * 8] =
                *(const uint4*)(Aps[s] + (size_t)(bm + row) * K + k0 + half * 8);
            *(uint4*)&sB[s][row][half * 8] =
                *(const uint4*)(Bps[s] + (size_t)(bn + row) * K + k0 + half * 8);
        }
        __syncthreads();

#pragma unroll
        for (int sa = 0; sa < 3; sa++) {
            wmma::fragment<wmma::matrix_a, 16, 16, 16, __nv_bfloat16, wmma::row_major> af[2];
#pragma unroll
            for (int mf = 0; mf < 2; mf++)
                wmma::load_matrix_sync(af[mf], &sA[sa][wm * 32 + mf * 16][0], WLDM);
#pragma unroll
            for (int sb = 0; sb < 3; sb++) {
                if (sa + sb > 2) break;   // 6 products: sa+sb <= 2
                wmma::fragment<wmma::matrix_b, 16, 16, 16, __nv_bfloat16, wmma::col_major> bf;
#pragma unroll
                for (int nf = 0; nf < 4; nf++) {
                    wmma::load_matrix_sync(bf, &sB[sb][wn * 64 + nf * 16][0], WLDM);
                    wmma::mma_sync(acc[0][nf], af[0], bf, acc[0][nf]);
                    wmma::mma_sync(acc[1][nf], af[1], bf, acc[1][nf]);
                }
            }
        }
        __syncthreads();
    }

    // epilogue: stage each 16x16 frag via smem, add bias (+relu), emit
#pragma unroll
    for (int mf = 0; mf < 2; mf++) {
#pragma unroll
        for (int nf = 0; nf < 4; nf++) {
            wmma::store_matrix_sync(&stage[wid][0], acc[mf][nf], 16, wmma::mem_row_major);
            __syncwarp();
#pragma unroll
            for (int e = 0; e < 8; e++) {
                int idx = lid * 8 + e;
                int r = idx >> 4, c = idx & 15;
                int grow = bm + wm * 32 + mf * 16 + r;
                int gcol = bn + wn * 64 + nf * 16 + c;
                float v = stage[wid][idx] + bias[gcol];
                if (outF) {
                    outF[(size_t)grow * NFull + gcol] = v;
                } else {
                    if (doRelu) v = fmaxf(v, 0.0f);
                    __nv_bfloat16 s0, s1, s2;
                    split3(v, s0, s1, s2);
                    size_t o = (size_t)grow * NFull + gcol;
                    o0[o] = s0; o1[o] = s1; o2[o] = s2;
                }
            }
            __syncwarp();
        }
    }
}

// ---------------- conversion kernels ----------------
__global__ __launch_bounds__(256)
void conv_x(const float* __restrict__ x)
{
    size_t i = (size_t)blockIdx.x * 256 + threadIdx.x;
    if (i == 0) g_maxbits = 0u;
    __nv_bfloat16 s0, s1, s2;
    split3(x[i], s0, s1, s2);
    g_xs[0][i] = s0; g_xs[1][i] = s1; g_xs[2][i] = s2;
}

__global__ __launch_bounds__(256)
void conv_wt(const float* __restrict__ w, __nv_bfloat16* __restrict__ t0,
             __nv_bfloat16* __restrict__ t1, __nv_bfloat16* __restrict__ t2,
             int N, int kShift)
{
    int idx = blockIdx.x * 256 + threadIdx.x;      // idx = n*K + k
    int K = 1 << kShift;
    int n = idx >> kShift, k = idx & (K - 1);
    __nv_bfloat16 s0, s1, s2;
    split3(w[(size_t)k * N + n], s0, s1, s2);
    t0[idx] = s0; t1[idx] = s1; t2[idx] = s2;
}

__global__ __launch_bounds__(256)
void conv_wpad(const float* __restrict__ wc, const float* __restrict__ bc,
               const float* __restrict__ wr, const float* __restrict__ br)
{
    int idx = blockIdx.x * 256 + threadIdx.x;      // 128*512: idx = n*512 + k
    int n = idx >> 9, k = idx & 511;
    float v = 0.0f;
    if (n < NUM_C)       v = wc[(size_t)k * NUM_C + n];
    else if (n < 110)    v = wr[(size_t)k * (NUM_C * 9) + (n - NUM_C)];
    __nv_bfloat16 s0, s1, s2;
    split3(v, s0, s1, s2);
    g_wtp[0][idx] = s0; g_wtp[1][idx] = s1; g_wtp[2][idx] = s2;
    if (idx < 128) {
        float b = 0.0f;
        if (idx < NUM_C)     b = bc[idx];
        else if (idx < 110)  b = br[idx - NUM_C];
        g_bpad[idx] = b;
    }
}

// ---------------- softmax + box decode + candidate build ----------------
__global__ __launch_bounds__(256)
void decode_kernel(const float* __restrict__ proposals)
{
    const int tid = blockIdx.x * blockDim.x + threadIdx.x;
    const int c  = tid >> 15;
    const int bn = tid & 32767;
    const int b  = bn >> 14;
    const int n  = bn & 16383;

    const float* hrow = g_h1 + (size_t)bn * 128;
    float l[NUM_C];
#pragma unroll
    for (int i = 0; i < NUM_C; i++) l[i] = hrow[i];
    float m = l[0];
#pragma unroll
    for (int i = 1; i < NUM_C; i++) m = fmaxf(m, l[i]);
    float sum = 0.0f;
#pragma unroll
    for (int i = 0; i < NUM_C; i++) sum += expf(l[i] - m);
    float score = expf(l[c + 1] - m) / sum;

    const float* p = proposals + (size_t)bn * 9;
    float w  = p[2] - p[0], h = p[3] - p[1];
    float cx = p[0] + 0.5f * w, cy = p[1] + 0.5f * h;
    const float* r = hrow + NUM_C + (c + 1) * 9;
    const float CLIP = 4.135166556742356f;
    float dx = r[0] / 10.0f, dy = r[1] / 10.0f;
    float dw = fminf(r[2] / 5.0f, CLIP), dh = fminf(r[3] / 5.0f, CLIP);
    float pcx = dx * w + cx, pcy = dy * h + cy;
    float pw = expf(dw) * w, ph = expf(dh) * h;
    float x1 = pcx - 0.5f * pw, y1 = pcy - 0.5f * ph;
    float x2 = pcx + 0.5f * pw, y2 = pcy + 0.5f * ph;

    const int cand = b * CAND + c * NUM_N + n;
    g_box4[cand] = make_float4(x1, y1, x2, y2);
    float* b9 = g_box9 + (size_t)cand * 9;
    b9[0] = x1; b9[1] = y1; b9[2] = x2; b9[3] = y2;
#pragma unroll
    for (int j = 0; j < 5; j++) b9[4 + j] = p[4 + j] + r[4 + j];

    float bw = x2 - x1, bh = y2 - y1;
    bool valid = (score > 0.05f) && (bw >= 0.01f) && (bh >= 0.01f);
    g_raw[cand]  = score;
    g_mask[cand] = valid ? score : -INFINITY;

    float mc = fmaxf(fmaxf(fabsf(x1), fabsf(y1)), fmaxf(fabsf(x2), fabsf(y2)));
#pragma unroll
    for (int o = 16; o; o >>= 1)
        mc = fmaxf(mc, __shfl_xor_sync(0xffffffffu, mc, o));
    if ((threadIdx.x & 31) == 0) atomicMax(&g_maxbits, __float_as_uint(mc));
}

// ---------------- per-class LAZY greedy NMS (proven R13-15) ----------------
__device__ __forceinline__ unsigned long long packkey(float v, unsigned idx) {
    unsigned u = __float_as_uint(v);
    u = (u & 0x80000000u) ? ~u : (u | 0x80000000u);
    return ((unsigned long long)u << 32) | (unsigned long long)(0xFFFFFFFFu - idx);
}
__device__ __forceinline__ float keyval(unsigned long long k) {
    unsigned u = (unsigned)(k >> 32);
    u = (u & 0x80000000u) ? (u & 0x7FFFFFFFu) : ~u;
    return __uint_as_float(u);
}

__global__ __launch_bounds__(256)
void nms_class(int startK, int endK)
{
    const int c = blockIdx.x;
    const int f = blockIdx.y;
    if (startK > 0 && !g_need[f][c]) return;

    const int tid = threadIdx.x;
    float* sc = g_mask + (size_t)f * CAND + (size_t)c * SEG;
    const float4* bx = g_box4 + (size_t)f * CAND + (size_t)c * SEG;
    const float off = (float)(c + 1) * (__uint_as_float(g_maxbits) + 1.0f);

    __shared__ float chmax[SCHUNK];
    __shared__ unsigned long long warpKeys[8];
    __shared__ float4 pbox[NUM_K];
    __shared__ int sK, sPcnt, sDone;

    if (tid == 0) { sK = startK; sPcnt = startK; sDone = 0; }
    if (tid < startK) pbox[tid] = g_pick[f][c][tid];

    {
        const float4* p4 = (const float4*)(sc + tid * 64);
        float m = -INFINITY;
#pragma unroll
        for (int q = 0; q < 16; q++) {
            float4 v = p4[q];
            m = fmaxf(m, fmaxf(fmaxf(v.x, v.y), fmaxf(v.z, v.w)));
        }
        chmax[tid] = m;
    }
    __syncthreads();

    while (true) {
        unsigned long long key = packkey(chmax[tid], (unsigned)tid);
#pragma unroll
        for (int o = 16; o; o >>= 1) {
            unsigned long long other = __shfl_xor_sync(0xffffffffu, key, o);
            if (other > key) key = other;
        }
        if ((tid & 31) == 0) warpKeys[tid >> 5] = key;
        __syncthreads();

        if (tid < 32) {
            unsigned long long kk = (tid < 8) ? warpKeys[tid] : 0ull;
#pragma unroll
            for (int o = 4; o; o >>= 1) {
                unsigned long long other = __shfl_xor_sync(0xffffffffu, kk, o);
                if (other > kk) kk = other;
            }
            kk = __shfl_sync(0xffffffffu, kk, 0);

            if (keyval(kk) == -INFINITY) {
                if (tid == 0) sDone = 1;
            } else {
                const int bestCh = (int)(0xFFFFFFFFu - (unsigned)(kk & 0xFFFFFFFFull));
                const int base = bestCh * 64;
                float s1 = sc[base + tid];
                float s2 = sc[base + tid + 32];
                unsigned long long k1 = packkey(s1, (unsigned)(base + tid));
                unsigned long long k2 = packkey(s2, (unsigned)(base + tid + 32));
                unsigned long long km = (k1 > k2) ? k1 : k2;
#pragma unroll
                for (int o = 16; o; o >>= 1) {
                    unsigned long long other = __shfl_xor_sync(0xffffffffu, km, o);
                    if (other > km) km = other;
                }
                km = __shfl_sync(0xffffffffu, km, 0);
                const int i = (int)(0xFFFFFFFFu - (unsigned)(km & 0xFFFFFFFFull));

                float4 bb = bx[i];
                float jx1 = bb.x + off, jy1 = bb.y + off;
                float jx2 = bb.z + off, jy2 = bb.w + off;
                float jb = (jx2 - jx1) * (jy2 - jy1);

                const int pc = sPcnt;
                int sup = 0;
                for (int p0 = 0; p0 < pc; p0 += 32) {
                    float iou = -1.0f;
                    int p = p0 + tid;
                    if (p < pc) {
                        float4 P = pbox[p];
                        float pa = (P.z - P.x) * (P.w - P.y);
                        float ix1 = fmaxf(P.x, jx1), iy1 = fmaxf(P.y, jy1);
                        float ix2 = fminf(P.z, jx2), iy2 = fminf(P.w, jy2);
                        float inter = fmaxf(ix2 - ix1, 0.0f) * fmaxf(iy2 - iy1, 0.0f);
                        iou = inter / (pa + jb - inter + 1e-9f);
                    }
                    sup |= (int)__any_sync(0xffffffffu, iou > 0.5f);
                }

                if (tid == 0) sc[i] = -INFINITY;
                float m1 = (base + tid == i)      ? -INFINITY : s1;
                float m2 = (base + tid + 32 == i) ? -INFINITY : s2;
                float mm = fmaxf(m1, m2);
#pragma unroll
                for (int o = 16; o; o >>= 1)
                    mm = fmaxf(mm, __shfl_xor_sync(0xffffffffu, mm, o));

                if (tid == 0) {
                    chmax[bestCh] = mm;
                    if (!sup) {
                        float4 pb = make_float4(jx1, jy1, jx2, jy2);
                        pbox[sPcnt] = pb;
                        g_pick[f][c][sPcnt] = pb;
                        g_keys[f][c][sK] = (km & 0xFFFFFFFF00000000ull) |
                            (unsigned long long)(0xFFFFFFFFu - (unsigned)(c * SEG + i));
                        sPcnt++; sK++;
                    }
                }
            }
        }
        __syncthreads();
        if (sDone || sK >= endK) break;
    }

    if (tid == 0) g_cnt[f][c] = sK;
}

// ---------------- merge check ----------------
__global__ __launch_bounds__(256)
void merge_check()
{
    const int f = blockIdx.x;
    const int tid = threadIdx.x;
    __shared__ unsigned long long keys[NCLS * PHASE1];
    __shared__ int cnts[NCLS];
    __shared__ unsigned long long sKth;
    __shared__ int sTotal;

    if (tid == 0) { sKth = 0ull; sTotal = 0; }
    if (tid < NCLS) cnts[tid] = g_cnt[f][tid];
    __syncthreads();
    for (int t = tid; t < NCLS * PHASE1; t += 256) {
        int c = t / PHASE1, k = t - c * PHASE1;
        keys[t] = (k < cnts[c]) ? g_keys[f][c][k] : 0ull;
    }
    __syncthreads();
    for (int t = tid; t < NCLS * PHASE1; t += 256) {
        unsigned long long mine = keys[t];
        if (mine != 0ull) {
            int rank = 0;
            for (int j = 0; j < NCLS * PHASE1; j++)
                if (keys[j] > mine) rank++;
            atomicAdd(&sTotal, 1);
            if (rank == NUM_K - 1) sKth = mine;
        }
    }
    __syncthreads();
    unsigned long long kth = (sTotal >= NUM_K) ? sKth : 0ull;
    if (tid < NCLS)
        g_need[f][tid] = (cnts[tid] == PHASE1) &&
                         (g_keys[f][tid][PHASE1 - 1] > kth);
}

// ---------------- final merge + emit ----------------
__global__ __launch_bounds__(1024)
void merge_emit(float* __restrict__ out)
{
    const int f = blockIdx.x;
    const int tid = threadIdx.x;
    __shared__ unsigned long long keys[NCLS * NUM_K];
    __shared__ int cnts[NCLS];
    __shared__ int sIdx[NUM_K];
    __shared__ unsigned long long sKey[NUM_K];
    __shared__ int sTotal;

    if (tid == 0) sTotal = 0;
    if (tid < NCLS) cnts[tid] = g_cnt[f][tid];
    if (tid < NUM_K) { sIdx[tid] = 0; sKey[tid] = 0ull; }
    __syncthreads();
    if (tid < NCLS * NUM_K) {
        int c = tid / NUM_K, k = tid - c * NUM_K;
        keys[tid] = (k < cnts[c]) ? g_keys[f][c][k] : 0ull;
    }
    __syncthreads();
    if (tid < NCLS * NUM_K) {
        unsigned long long mine = keys[tid];
        if (mine != 0ull) {
            int rank = 0;
            for (int j = 0; j < NCLS * NUM_K; j++)
                if (keys[j] > mine) rank++;
            atomicAdd(&sTotal, 1);
            if (rank < NUM_K) {
                sKey[rank] = mine;
                sIdx[rank] = (int)(0xFFFFFFFFu - (unsigned)(mine & 0xFFFFFFFFull));
            }
        }
    }
    __syncthreads();

    const float* b9  = g_box9 + (size_t)f * CAND * 9;
    const float* raw = g_raw  + (size_t)f * CAND;
    for (int t = tid; t < NUM_K * 9; t += 1024) {
        int k = t / 9, j = t - k * 9;
        int i = sIdx[k];
        out[((size_t)f * NUM_K + k) * 9 + j] = b9[(size_t)i * 9 + j];
    }
    if (tid < NUM_K) {
        int i = sIdx[tid];
        bool pick = (sKey[tid] != 0ull);
        out[NUM_B * NUM_K * 9 + f * NUM_K + tid] = pick ? raw[i] : 0.0f;
        out[NUM_B * NUM_K * 9 + NUM_B * NUM_K + f * NUM_K + tid] =
            pick ? (float)((i >> 14) + 1) : -1.0f;
    }
}

// ---------------- launch ----------------
extern "C" void kernel_launch(void* const* d_in, const int* in_sizes, int n_in,
                              void* d_out, int out_size)
{
    const float* x  = (const float*)d_in[0];
    const float* pr = (const float*)d_in[1];
    const float* w1 = (const float*)d_in[2];
    const float* b1 = (const float*)d_in[3];
    const float* w2 = (const float*)d_in[4];
    const float* b2 = (const float*)d_in[5];
    const float* wc = (const float*)d_in[6];
    const float* bc = (const float*)d_in[7];
    const float* wr = (const float*)d_in[8];
    const float* br = (const float*)d_in[9];
    float* out = (float*)d_out;

    void *xs, *h1s, *h2s, *wt1, *wt2, *wtp, *bpad, *h1;
    cudaGetSymbolAddress(&xs, g_xs);
    cudaGetSymbolAddress(&h1s, g_h1s);
    cudaGetSymbolAddress(&h2s, g_h2s);
    cudaGetSymbolAddress(&wt1, g_wt1);
    cudaGetSymbolAddress(&wt2, g_wt2);
    cudaGetSymbolAddress(&wtp, g_wtp);
    cudaGetSymbolAddress(&bpad, g_bpad);
    cudaGetSymbolAddress(&h1, g_h1);

    __nv_bfloat16* xsp  = (__nv_bfloat16*)xs;
    __nv_bfloat16* h1sp = (__nv_bfloat16*)h1s;
    __nv_bfloat16* h2sp = (__nv_bfloat16*)h2s;
    __nv_bfloat16* wt1p = (__nv_bfloat16*)wt1;
    __nv_bfloat16* wt2p = (__nv_bfloat16*)wt2;
    __nv_bfloat16* wtpp = (__nv_bfloat16*)wtp;
    const size_t XL   = (size_t)ROWS * NUM_DIN;
    const size_t H1L  = (size_t)ROWS * NUM_H;
    const size_t WT1L = (size_t)NUM_H * NUM_DIN;
    const size_t WT2L = (size_t)NUM_H * NUM_H;
    const size_t WTPL = (size_t)128 * NUM_H;

    // 1-3: conversions (conv_x also zeroes g_maxbits)
    conv_x<<<(ROWS * NUM_DIN) / 256, 256>>>(x);
    conv_wt<<<(NUM_H * NUM_DIN) / 256, 256>>>(w1, wt1p, wt1p + WT1L, wt1p + 2 * WT1L,
                                              NUM_H, 10);
    conv_wt<<<(NUM_H * NUM_H) / 256, 256>>>(w2, wt2p, wt2p + WT2L, wt2p + 2 * WT2L,
                                            NUM_H, 9);
    // 4 (profiled slot): gemm1 = relu(x@w1+b1) -> h1 splits
    gemm_wmma<<<dim3(NUM_H / 128, ROWS / 128), 256>>>(
        xsp, xsp + XL, xsp + 2 * XL,
        wt1p, wt1p + WT1L, wt1p + 2 * WT1L,
        b1, NUM_DIN, NUM_H, nullptr, h1sp, h1sp + H1L, h1sp + 2 * H1L, 1);
    // 5: pack head weights/bias
    conv_wpad<<<(128 * NUM_H) / 256, 256>>>(wc, bc, wr, br);
    // 6: gemm2 = relu(h1@w2+b2) -> h2 splits
    gemm_wmma<<<dim3(NUM_H / 128, ROWS / 128), 256>>>(
        h1sp, h1sp + H1L, h1sp + 2 * H1L,
        wt2p, wt2p + WT2L, wt2p + 2 * WT2L,
        b2, NUM_H, NUM_H, nullptr, h2sp, h2sp + H1L, h2sp + 2 * H1L, 1);
    // 7: heads = h2@[wc|wr]+bias -> g_h1 fp32 [ROWS,128]
    gemm_wmma<<<dim3(1, ROWS / 128), 256>>>(
        h2sp, h2sp + H1L, h2sp + 2 * H1L,
        wtpp, wtpp + WTPL, wtpp + 2 * WTPL,
        (const float*)bpad, NUM_H, 128, (float*)h1, nullptr, nullptr, nullptr, 0);
    // 8: decode
    decode_kernel<<<(ROWS * (NUM_C - 1)) / 256, 256>>>(pr);
    // 9-12: lazy per-class NMS + exact merge
    nms_class<<<dim3(NCLS, NUM_B), 256>>>(0, PHASE1);
    merge_check<<<NUM_B, 256>>>();
    nms_class<<<dim3(NCLS, NUM_B), 256>>>(PHASE1, NUM_K);
    merge_emit<<<NUM_B, 1024>>>(out);
}